// round 3
// baseline (speedup 1.0000x reference)
#include <cuda_runtime.h>
#include <cuda_bf16.h>
#include <stdint.h>

#define N_NODES 100000
#define IN_DIM  128
#define HID_DIM 64
#define OUT_DIM 128

// Scratch (allocation-free rule: __device__ globals)
__device__ __align__(16) float g_dinv[N_NODES];
__device__ __align__(16) float g_hs [(size_t)N_NODES * HID_DIM];
__device__ __align__(16) float g_acc[(size_t)N_NODES * HID_DIM];

__device__ __forceinline__ void fma4(float4& a, float s, const float4& b) {
    a.x = fmaf(s, b.x, a.x);
    a.y = fmaf(s, b.y, a.y);
    a.z = fmaf(s, b.z, a.z);
    a.w = fmaf(s, b.w, a.w);
}

// ---------------------------------------------------------------- degree pass
__global__ void init_dinv_kernel(int n) {
    int i = blockIdx.x * blockDim.x + threadIdx.x;
    if (i < n) g_dinv[i] = 1.0f;  // self-loop
}

__global__ void deg_kernel(const int* __restrict__ dst, int e) {
    int i = blockIdx.x * blockDim.x + threadIdx.x;
    if (i < e) atomicAdd(&g_dinv[dst[i]], 1.0f);
}

__global__ void final_dinv_kernel(int n) {
    int i = blockIdx.x * blockDim.x + threadIdx.x;
    if (i < n) g_dinv[i] = rsqrtf(g_dinv[i]);
}

// ---------------------------------------------------------------- GEMM1
// hs[r][c] = dinv[r] * sum_k x[r][k]*Wc[k][c];  write to g_hs AND g_acc (self-loop init)
// Tile M=32, N=64(all), K=128. 256 threads, each 2 rows x 4 cols.
__global__ __launch_bounds__(256) void gemm1_kernel(const float* __restrict__ x,
                                                    const float* __restrict__ Wc,
                                                    int n) {
    __shared__ float4 Xs[32 * 32];   // 32 rows x 128 floats, chunk-swizzled
    __shared__ float4 Ws[128 * 16];  // 128 x 64 floats
    const int t = threadIdx.x;
    const int rowBase = blockIdx.x * 32;

    // Load W_conv (8192 floats = 2048 float4)
    const float4* Wg = (const float4*)Wc;
    #pragma unroll
    for (int i = 0; i < 8; i++) Ws[t + i * 256] = Wg[t + i * 256];

    // Load X tile (32 rows x 128 = 1024 float4), swizzle chunk index by +row
    const float4* Xg = (const float4*)(x + (size_t)rowBase * IN_DIM);
    #pragma unroll
    for (int i = 0; i < 4; i++) {
        int idx = t + i * 256;
        int r = idx >> 5, c = idx & 31;
        float4 v = make_float4(0.f, 0.f, 0.f, 0.f);
        if (rowBase + r < n) v = Xg[idx];
        Xs[r * 32 + ((c + r) & 31)] = v;
    }
    __syncthreads();

    const int cg = t & 15;   // 16 col groups * 4 = 64 cols
    const int rg = t >> 4;   // 16 row groups * 2 = 32 rows
    float4 acc0 = make_float4(0.f,0.f,0.f,0.f);
    float4 acc1 = make_float4(0.f,0.f,0.f,0.f);

    #pragma unroll
    for (int k = 0; k < 128; k += 4) {
        float4 w0 = Ws[(k + 0) * 16 + cg];
        float4 w1 = Ws[(k + 1) * 16 + cg];
        float4 w2 = Ws[(k + 2) * 16 + cg];
        float4 w3 = Ws[(k + 3) * 16 + cg];
        {
            int r = rg * 2;
            float4 xv = Xs[r * 32 + (((k >> 2) + r) & 31)];
            fma4(acc0, xv.x, w0); fma4(acc0, xv.y, w1);
            fma4(acc0, xv.z, w2); fma4(acc0, xv.w, w3);
        }
        {
            int r = rg * 2 + 1;
            float4 xv = Xs[r * 32 + (((k >> 2) + r) & 31)];
            fma4(acc1, xv.x, w0); fma4(acc1, xv.y, w1);
            fma4(acc1, xv.z, w2); fma4(acc1, xv.w, w3);
        }
    }

    #pragma unroll
    for (int i = 0; i < 2; i++) {
        int r = rowBase + rg * 2 + i;
        if (r < n) {
            float dv = g_dinv[r];
            float4 a = (i == 0) ? acc0 : acc1;
            a.x *= dv; a.y *= dv; a.z *= dv; a.w *= dv;
            size_t off = (size_t)r * HID_DIM + cg * 4;
            *(float4*)&g_hs[off]  = a;
            *(float4*)&g_acc[off] = a;
        }
    }
}

// ---------------------------------------------------------------- edge scatter
// 8 threads per edge; each does 2x (LDG.128 gather + red.global.add.v4.f32)
__global__ __launch_bounds__(256) void scatter_kernel(const int* __restrict__ src,
                                                      const int* __restrict__ dst,
                                                      int e) {
    int gid = blockIdx.x * blockDim.x + threadIdx.x;
    int eid = gid >> 3;
    if (eid >= e) return;
    int g = gid & 7;
    int s = __ldg(&src[eid]);
    int d = __ldg(&dst[eid]);
    const float4* a = (const float4*)&g_hs[(size_t)s * HID_DIM + g * 8];
    float4 v0 = a[0];
    float4 v1 = a[1];
    float* p = &g_acc[(size_t)d * HID_DIM + g * 8];
    asm volatile("red.global.add.v4.f32 [%0], {%1,%2,%3,%4};"
                 :: "l"(p), "f"(v0.x), "f"(v0.y), "f"(v0.z), "f"(v0.w) : "memory");
    asm volatile("red.global.add.v4.f32 [%0], {%1,%2,%3,%4};"
                 :: "l"(p + 4), "f"(v1.x), "f"(v1.y), "f"(v1.z), "f"(v1.w) : "memory");
}

// ---------------------------------------------------------------- GEMM2 (fused)
// h2[r][k] = relu(dinv[r]*acc[r][k] + bconv[k]);  out = h2 @ Wlin + blin
// Tile M=32, N=128(all), K=64. 256 threads, each 4 rows x 4 cols.
__global__ __launch_bounds__(256) void gemm2_kernel(const float* __restrict__ Wlin,
                                                    const float* __restrict__ bconv,
                                                    const float* __restrict__ blin,
                                                    float* __restrict__ out,
                                                    int n) {
    __shared__ float4 Hs[32 * 16];   // 32 rows x 64 floats
    __shared__ float4 Ws[64 * 32];   // 64 x 128 floats
    __shared__ float4 Bl[32];        // 128 floats
    const int t = threadIdx.x;
    const int rowBase = blockIdx.x * 32;

    // W_lin: 8192 floats = 2048 float4
    const float4* Wg = (const float4*)Wlin;
    #pragma unroll
    for (int i = 0; i < 8; i++) Ws[t + i * 256] = Wg[t + i * 256];
    if (t < 32) Bl[t] = ((const float4*)blin)[t];

    // acc tile: 32 rows x 64 = 512 float4; apply norm + bias + relu
    #pragma unroll
    for (int i = 0; i < 2; i++) {
        int idx = t + i * 256;
        int r = idx >> 4, c = idx & 15;
        int row = rowBase + r;
        float4 v = make_float4(0.f, 0.f, 0.f, 0.f);
        if (row < n) {
            v = *(const float4*)&g_acc[(size_t)row * HID_DIM + c * 4];
            float dv = g_dinv[row];
            float4 b = __ldg((const float4*)&bconv[c * 4]);
            v.x = fmaxf(fmaf(v.x, dv, b.x), 0.f);
            v.y = fmaxf(fmaf(v.y, dv, b.y), 0.f);
            v.z = fmaxf(fmaf(v.z, dv, b.z), 0.f);
            v.w = fmaxf(fmaf(v.w, dv, b.w), 0.f);
        }
        Hs[r * 16 + c] = v;  // row broadcast in compute phase -> no swizzle needed
    }
    __syncthreads();

    const int cg = t & 31;   // 32 col groups * 4 = 128 cols
    const int rg = t >> 5;   // 8 row groups * 4 = 32 rows
    float4 acc[4];
    #pragma unroll
    for (int i = 0; i < 4; i++) acc[i] = make_float4(0.f,0.f,0.f,0.f);

    #pragma unroll
    for (int k = 0; k < 64; k += 4) {
        float4 w0 = Ws[(k + 0) * 32 + cg];
        float4 w1 = Ws[(k + 1) * 32 + cg];
        float4 w2 = Ws[(k + 2) * 32 + cg];
        float4 w3 = Ws[(k + 3) * 32 + cg];
        #pragma unroll
        for (int i = 0; i < 4; i++) {
            float4 xv = Hs[(rg * 4 + i) * 16 + (k >> 2)];
            fma4(acc[i], xv.x, w0); fma4(acc[i], xv.y, w1);
            fma4(acc[i], xv.z, w2); fma4(acc[i], xv.w, w3);
        }
    }

    float4 bl = Bl[cg];
    #pragma unroll
    for (int i = 0; i < 4; i++) {
        int row = rowBase + rg * 4 + i;
        if (row < n) {
            float4 o = acc[i];
            o.x += bl.x; o.y += bl.y; o.z += bl.z; o.w += bl.w;
            *(float4*)&out[(size_t)row * OUT_DIM + cg * 4] = o;
        }
    }
}

// ---------------------------------------------------------------- launch
extern "C" void kernel_launch(void* const* d_in, const int* in_sizes, int n_in,
                              void* d_out, int out_size) {
    const float* x     = (const float*)d_in[0];
    const int*   ei    = (const int*)  d_in[1];
    const float* Wc    = (const float*)d_in[2];
    const float* bc    = (const float*)d_in[3];
    const float* Wl    = (const float*)d_in[4];
    const float* bl    = (const float*)d_in[5];
    float*       out   = (float*)d_out;

    const int n = in_sizes[0] / IN_DIM;      // 100000
    const int e = in_sizes[1] / 2;           // 1600000
    const int* src = ei;
    const int* dst = ei + e;

    init_dinv_kernel <<<(n + 255) / 256, 256>>>(n);
    deg_kernel       <<<(e + 255) / 256, 256>>>(dst, e);
    final_dinv_kernel<<<(n + 255) / 256, 256>>>(n);
    gemm1_kernel     <<<(n + 31) / 32, 256>>>(x, Wc, n);
    {
        long long threads = (long long)e * 8;
        int blocks = (int)((threads + 255) / 256);
        scatter_kernel<<<blocks, 256>>>(src, dst, e);
    }
    gemm2_kernel     <<<(n + 31) / 32, 256>>>(Wl, bc, bl, out, n);
}